// round 6
// baseline (speedup 1.0000x reference)
#include <cuda_runtime.h>

#define NN   50000
#define NE   800000
#define DD   64
#define NG   512
#define ODIM 24
#define NB   196   // scan blocks: 196*256 = 50176 >= NN

// ---------------- device scratch ----------------
__device__ float d_P[NN * DD];
__device__ float d_M[NN * DD];
__device__ float d_H0[NN * DD];
__device__ float d_H1[NN * DD];
__device__ float d_H2[NN * DD];
__device__ int   d_csr[NE];
__device__ int   d_off[NN + 1];
__device__ int   d_cur[NN];
__device__ int   d_bsum[256];
__device__ float d_G[NG * 192];
__device__ int   d_gs[NG + 1];

// ---------------- f32x2 helpers ----------------
typedef unsigned long long u64v;
__device__ __forceinline__ u64v pack2(float lo, float hi) {
    u64v r;
    asm("mov.b64 %0, {%1,%2};" : "=l"(r) : "r"(__float_as_uint(lo)), "r"(__float_as_uint(hi)));
    return r;
}
__device__ __forceinline__ u64v ffma2(u64v a, u64v b, u64v c) {
    u64v d;
    asm("fma.rn.f32x2 %0, %1, %2, %3;" : "=l"(d) : "l"(a), "l"(b), "l"(c));
    return d;
}
__device__ __forceinline__ float2 unpk2(u64v p) {
    unsigned lo, hi;
    asm("mov.b64 {%0,%1}, %2;" : "=r"(lo), "=r"(hi) : "l"(p));
    return make_float2(__uint_as_float(lo), __uint_as_float(hi));
}

// ---------------- setup: zero counters/G + graph segment starts ----------------
__global__ void k_setup(const int* __restrict__ batch) {
    int i = blockIdx.x * blockDim.x + threadIdx.x;   // 196*256 = 50176 threads
    if (i < NN) d_cur[i] = 0;
    // zero d_G (98304 floats <= 2*50176)
    if (i < NG * 192) d_G[i] = 0.f;
    int j = i + 50176;
    if (j < NG * 192) d_G[j] = 0.f;
    // graph starts (first 513 threads)
    if (i <= NG) {
        int g = i, lo = 0, hi = NN;
        while (lo < hi) {
            int mid = (lo + hi) >> 1;
            if (batch[mid] < g) lo = mid + 1; else hi = mid;
        }
        d_gs[g] = lo;
    }
}

__global__ void k_hist(const int* __restrict__ ei) {
    int e = blockIdx.x * blockDim.x + threadIdx.x;
    if (e < NE) atomicAdd(&d_cur[ei[NE + e]], 1);
}

// ---------------- 3-phase scan ----------------
__global__ void k_scan1() {
    __shared__ int sh[256];
    int t = threadIdx.x;
    int i = blockIdx.x * 256 + t;
    int v = (i < NN) ? d_cur[i] : 0;
    sh[t] = v;
    __syncthreads();
    for (int s = 1; s < 256; s <<= 1) {
        int x = (t >= s) ? sh[t - s] : 0;
        __syncthreads();
        sh[t] += x;
        __syncthreads();
    }
    if (i < NN) d_off[i] = sh[t] - v;
    if (t == 255) d_bsum[blockIdx.x] = sh[255];
}

__global__ void k_scan2() {
    __shared__ int sh[256];
    int t = threadIdx.x;
    int v = (t < NB) ? d_bsum[t] : 0;
    sh[t] = v;
    __syncthreads();
    for (int s = 1; s < 256; s <<= 1) {
        int x = (t >= s) ? sh[t - s] : 0;
        __syncthreads();
        sh[t] += x;
        __syncthreads();
    }
    if (t < NB) d_bsum[t] = sh[t] - v;
    if (t == 255) d_off[NN] = sh[255];
}

__global__ void k_scan3() {
    int i = blockIdx.x * 256 + threadIdx.x;
    if (i < NN) {
        int o = d_off[i] + d_bsum[blockIdx.x];
        d_off[i] = o;
        d_cur[i] = o;
    }
}

__global__ void k_fill(const int* __restrict__ ei) {
    int e = blockIdx.x * blockDim.x + threadIdx.x;
    if (e < NE) {
        int s = ei[e];
        int d = ei[NE + e];
        int p = atomicAdd(&d_cur[d], 1);
        d_csr[p] = s;
    }
}

// ---------------- SGEMM (FFMA2): C[N,64] = A[N,K] @ W[K,64] (+bias,relu,+pool) ----------------
template <int K, bool BIAS_RELU, bool POOL>
__global__ __launch_bounds__(256) void k_gemm(const float* __restrict__ A,
                                              const float* __restrict__ W,
                                              const float* __restrict__ bias,
                                              float* __restrict__ C,
                                              const int* __restrict__ batch,
                                              int lofs) {
    constexpr int KQ = K / 4;
    constexpr int SA = 130;                 // transposed-A row stride (even for b64 loads)
    extern __shared__ float sm[];
    float* Ws  = sm;                        // [K][64]
    float* AsT = sm + K * 64;               // [K][SA] transposed (k-major)
    int tid = threadIdx.x;
    int row0 = blockIdx.x * 128;

    for (int i = tid; i < K * 16; i += 256)
        ((float4*)Ws)[i] = ((const float4*)W)[i];
    for (int i = tid; i < 128 * KQ; i += 256) {
        int r  = i / KQ;
        int kq = (i % KQ) * 4;
        float4 v = make_float4(0.f, 0.f, 0.f, 0.f);
        int row = row0 + r;
        if (row < NN) v = *(const float4*)&A[(long)row * K + kq];
        AsT[(kq + 0) * SA + r] = v.x;
        AsT[(kq + 1) * SA + r] = v.y;
        AsT[(kq + 2) * SA + r] = v.z;
        AsT[(kq + 3) * SA + r] = v.w;
    }
    __syncthreads();

    int tx = tid & 15, ty = tid >> 4;
    int rb = ty * 8, cb = tx * 4;

    u64v acc[4][4];                          // 4 row-pairs x 4 cols
#pragma unroll
    for (int p = 0; p < 4; p++)
#pragma unroll
        for (int j = 0; j < 4; j++) acc[p][j] = pack2(0.f, 0.f);

#pragma unroll 4
    for (int k = 0; k < K; k++) {
        float4 w = *(float4*)&Ws[k * 64 + cb];
        u64v wx = pack2(w.x, w.x);
        u64v wy = pack2(w.y, w.y);
        u64v wz = pack2(w.z, w.z);
        u64v ww = pack2(w.w, w.w);
        const float* ar = &AsT[k * SA + rb];
#pragma unroll
        for (int p = 0; p < 4; p++) {
            u64v a = *(const u64v*)(ar + 2 * p);
            acc[p][0] = ffma2(a, wx, acc[p][0]);
            acc[p][1] = ffma2(a, wy, acc[p][1]);
            acc[p][2] = ffma2(a, wz, acc[p][2]);
            acc[p][3] = ffma2(a, ww, acc[p][3]);
        }
    }

    float4 bv;
    if (BIAS_RELU) bv = *(const float4*)&bias[cb];

    int   curb = -1;
    float4 rs = make_float4(0.f, 0.f, 0.f, 0.f);

#pragma unroll
    for (int p = 0; p < 4; p++) {
        float2 c0 = unpk2(acc[p][0]);
        float2 c1 = unpk2(acc[p][1]);
        float2 c2 = unpk2(acc[p][2]);
        float2 c3 = unpk2(acc[p][3]);
#pragma unroll
        for (int h = 0; h < 2; h++) {
            int row = row0 + rb + 2 * p + h;
            if (row >= NN) continue;
            float4 o;
            o.x = h ? c0.y : c0.x;
            o.y = h ? c1.y : c1.x;
            o.z = h ? c2.y : c2.x;
            o.w = h ? c3.y : c3.x;
            if (BIAS_RELU) {
                o.x = fmaxf(o.x + bv.x, 0.f);
                o.y = fmaxf(o.y + bv.y, 0.f);
                o.z = fmaxf(o.z + bv.z, 0.f);
                o.w = fmaxf(o.w + bv.w, 0.f);
            }
            *(float4*)&C[(long)row * 64 + cb] = o;
            if (POOL) {
                int b = batch[row];
                if (b != curb) {
                    if (curb >= 0) {
                        float* g = &d_G[curb * 192 + lofs + cb];
                        atomicAdd(g + 0, rs.x);
                        atomicAdd(g + 1, rs.y);
                        atomicAdd(g + 2, rs.z);
                        atomicAdd(g + 3, rs.w);
                    }
                    curb = b;
                    rs = make_float4(0.f, 0.f, 0.f, 0.f);
                }
                rs.x += o.x; rs.y += o.y; rs.z += o.z; rs.w += o.w;
            }
        }
    }
    if (POOL && curb >= 0) {
        float* g = &d_G[curb * 192 + lofs + cb];
        atomicAdd(g + 0, rs.x);
        atomicAdd(g + 1, rs.y);
        atomicAdd(g + 2, rs.z);
        atomicAdd(g + 3, rs.w);
    }
}

// ---------------- aggregation: M[n] = relu(P[n] + sum_{e->n} P[src(e)] + b1) ----------------
__global__ __launch_bounds__(256) void k_agg(const float* __restrict__ bias) {
    int warp = (blockIdx.x * blockDim.x + threadIdx.x) >> 5;
    int lane = threadIdx.x & 31;
    if (warp >= NN) return;
    int n = warp;
    int e0 = d_off[n], e1 = d_off[n + 1];
    const float2* P2 = (const float2*)d_P;
    float2 acc = make_float2(0.f, 0.f);
    int eb = e0;
    for (; eb + 32 <= e1; eb += 32) {
        int sl = d_csr[eb + lane];
#pragma unroll
        for (int j = 0; j < 32; ++j) {
            int s = __shfl_sync(0xffffffffu, sl, j);
            float2 v = __ldg(&P2[s * 32 + lane]);
            acc.x += v.x;
            acc.y += v.y;
        }
    }
    int rem = e1 - eb;
    if (rem > 0) {
        int sl = (lane < rem) ? d_csr[eb + lane] : 0;
        for (int j = 0; j < rem; ++j) {
            int s = __shfl_sync(0xffffffffu, sl, j);
            float2 v = __ldg(&P2[s * 32 + lane]);
            acc.x += v.x;
            acc.y += v.y;
        }
    }
    float2 p = P2[n * 32 + lane];
    float2 b = ((const float2*)bias)[lane];
    float2 o;
    o.x = fmaxf(p.x + acc.x + b.x, 0.f);
    o.y = fmaxf(p.y + acc.y + b.y, 0.f);
    ((float2*)d_M)[n * 32 + lane] = o;
}

// ---------------- tail ----------------
__global__ __launch_bounds__(64) void k_tail(const float* __restrict__ jk_w,
                                             const float* __restrict__ jk_b,
                                             const float* __restrict__ fw1,
                                             const float* __restrict__ fb1,
                                             const float* __restrict__ bng,
                                             const float* __restrict__ bnb,
                                             const float* __restrict__ bnm,
                                             const float* __restrict__ bnv,
                                             const float* __restrict__ fw2,
                                             const float* __restrict__ fb2,
                                             const float* __restrict__ ow,
                                             const float* __restrict__ ob,
                                             float* __restrict__ out) {
    int g = blockIdx.x, j = threadIdx.x;
    __shared__ float sv[192];
    __shared__ float t[64];
    sv[j]       = d_G[g * 192 + j];
    sv[j + 64]  = d_G[g * 192 + j + 64];
    sv[j + 128] = d_G[g * 192 + j + 128];
    __syncthreads();
    float cnt = (float)(d_gs[g + 1] - d_gs[g]);
    float a = cnt * jk_b[j];
    for (int k = 0; k < 192; k++) a += sv[k] * jk_w[k * 64 + j];
    __syncthreads();
    t[j] = a;
    __syncthreads();
    float a2 = fb1[j];
    for (int k = 0; k < 64; k++) a2 += t[k] * fw1[k * 64 + j];
    a2 = (a2 - bnm[j]) * rsqrtf(bnv[j] + 1e-5f) * bng[j] + bnb[j];
    a2 = fmaxf(a2, 0.f);
    __syncthreads();
    t[j] = a2;
    __syncthreads();
    float a3 = fb2[j];
    for (int k = 0; k < 64; k++) a3 += t[k] * fw2[k * 64 + j];
    __syncthreads();
    t[j] = a3;
    __syncthreads();
    if (j < ODIM) {
        float o = ob[j];
        for (int k = 0; k < 64; k++) o += t[k] * ow[k * ODIM + j];
        out[g * ODIM + j] = o;
    }
}

// ---------------- launcher ----------------
extern "C" void kernel_launch(void* const* d_in, const int* in_sizes, int n_in,
                              void* d_out, int out_size) {
    const float* x     = (const float*)d_in[0];
    const int*   ei    = (const int*)d_in[1];
    const int*   batch = (const int*)d_in[2];
    const float* w1[3] = {(const float*)d_in[3],  (const float*)d_in[7],  (const float*)d_in[11]};
    const float* b1[3] = {(const float*)d_in[4],  (const float*)d_in[8],  (const float*)d_in[12]};
    const float* w2[3] = {(const float*)d_in[5],  (const float*)d_in[9],  (const float*)d_in[13]};
    const float* b2[3] = {(const float*)d_in[6],  (const float*)d_in[10], (const float*)d_in[14]};
    const float* jk_w  = (const float*)d_in[15];
    const float* jk_b  = (const float*)d_in[16];
    const float* fw1   = (const float*)d_in[17];
    const float* fb1   = (const float*)d_in[18];
    const float* bng   = (const float*)d_in[19];
    const float* bnb   = (const float*)d_in[20];
    const float* bnm   = (const float*)d_in[21];
    const float* bnv   = (const float*)d_in[22];
    const float* fw2   = (const float*)d_in[23];
    const float* fb2   = (const float*)d_in[24];
    const float* ow    = (const float*)d_in[25];
    const float* ob    = (const float*)d_in[26];
    float* out = (float*)d_out;

    float *P, *M, *H[3];
    cudaGetSymbolAddress((void**)&P,    d_P);
    cudaGetSymbolAddress((void**)&M,    d_M);
    cudaGetSymbolAddress((void**)&H[0], d_H0);
    cudaGetSymbolAddress((void**)&H[1], d_H1);
    cudaGetSymbolAddress((void**)&H[2], d_H2);

    size_t s100 = (size_t)(100 * 64 + 100 * 130) * sizeof(float);
    size_t s64  = (size_t)(64 * 64 + 64 * 130) * sizeof(float);
    cudaFuncSetAttribute((const void*)k_gemm<100, false, false>,
                         cudaFuncAttributeMaxDynamicSharedMemorySize, (int)s100);
    cudaFuncSetAttribute((const void*)k_gemm<64, false, false>,
                         cudaFuncAttributeMaxDynamicSharedMemorySize, (int)s64);
    cudaFuncSetAttribute((const void*)k_gemm<64, true, true>,
                         cudaFuncAttributeMaxDynamicSharedMemorySize, (int)s64);

    // setup + CSR build
    k_setup<<<NB, 256>>>(batch);
    k_hist<<<(NE + 255) / 256, 256>>>(ei);
    k_scan1<<<NB, 256>>>();
    k_scan2<<<1, 256>>>();
    k_scan3<<<NB, 256>>>();
    k_fill<<<(NE + 255) / 256, 256>>>(ei);

    int gemm_blocks = (NN + 127) / 128;
    int agg_blocks  = (NN * 32 + 255) / 256;

    // layer 0 (K=100 input)
    k_gemm<100, false, false><<<gemm_blocks, 256, s100>>>(x, w1[0], nullptr, P, nullptr, 0);
    k_agg<<<agg_blocks, 256>>>(b1[0]);
    k_gemm<64, true, true><<<gemm_blocks, 256, s64>>>(M, w2[0], b2[0], H[0], batch, 0);

    // layers 1, 2 (pool fused into w2-gemm epilogue)
    for (int li = 1; li < 3; ++li) {
        k_gemm<64, false, false><<<gemm_blocks, 256, s64>>>(H[li - 1], w1[li], nullptr, P, nullptr, 0);
        k_agg<<<agg_blocks, 256>>>(b1[li]);
        k_gemm<64, true, true><<<gemm_blocks, 256, s64>>>(M, w2[li], b2[li], H[li], batch, li * 64);
    }

    // head
    k_tail<<<NG, 64>>>(jk_w, jk_b, fw1, fb1, bng, bnb, bnm, bnv, fw2, fb2, ow, ob, out);
}

// round 7
// speedup vs baseline: 1.0107x; 1.0107x over previous
#include <cuda_runtime.h>

#define NN   50000
#define NE   800000
#define DD   64
#define NG   512
#define ODIM 24
#define NB   196   // scan blocks: 196*256 = 50176 >= NN

// ---------------- device scratch ----------------
__device__ float d_P[NN * DD];
__device__ float d_M[NN * DD];
__device__ float d_H0[NN * DD];
__device__ float d_H1[NN * DD];
__device__ float d_H2[NN * DD];
__device__ int   d_csr[NE];
__device__ int   d_off[NN + 1];
__device__ int   d_cur[NN];
__device__ int   d_bsum[256];
__device__ float d_G[NG * 192];
__device__ int   d_gs[NG + 1];

// ---------------- f32x2 helpers ----------------
typedef unsigned long long u64v;
__device__ __forceinline__ u64v pack2(float lo, float hi) {
    u64v r;
    asm("mov.b64 %0, {%1,%2};" : "=l"(r) : "r"(__float_as_uint(lo)), "r"(__float_as_uint(hi)));
    return r;
}
__device__ __forceinline__ u64v ffma2(u64v a, u64v b, u64v c) {
    u64v d;
    asm("fma.rn.f32x2 %0, %1, %2, %3;" : "=l"(d) : "l"(a), "l"(b), "l"(c));
    return d;
}
__device__ __forceinline__ float2 unpk2(u64v p) {
    unsigned lo, hi;
    asm("mov.b64 {%0,%1}, %2;" : "=r"(lo), "=r"(hi) : "l"(p));
    return make_float2(__uint_as_float(lo), __uint_as_float(hi));
}

// ---------------- setup: zero counters/G + graph segment starts ----------------
__global__ void k_setup(const int* __restrict__ batch) {
    int i = blockIdx.x * blockDim.x + threadIdx.x;   // 196*256 = 50176 threads
    if (i < NN) d_cur[i] = 0;
    // zero d_G (98304 floats <= 2*50176)
    if (i < NG * 192) d_G[i] = 0.f;
    int j = i + 50176;
    if (j < NG * 192) d_G[j] = 0.f;
    // graph starts (first 513 threads)
    if (i <= NG) {
        int g = i, lo = 0, hi = NN;
        while (lo < hi) {
            int mid = (lo + hi) >> 1;
            if (batch[mid] < g) lo = mid + 1; else hi = mid;
        }
        d_gs[g] = lo;
    }
}

__global__ void k_hist(const int* __restrict__ ei) {
    int e = blockIdx.x * blockDim.x + threadIdx.x;
    if (e < NE) atomicAdd(&d_cur[ei[NE + e]], 1);
}

// ---------------- 3-phase scan ----------------
__global__ void k_scan1() {
    __shared__ int sh[256];
    int t = threadIdx.x;
    int i = blockIdx.x * 256 + t;
    int v = (i < NN) ? d_cur[i] : 0;
    sh[t] = v;
    __syncthreads();
    for (int s = 1; s < 256; s <<= 1) {
        int x = (t >= s) ? sh[t - s] : 0;
        __syncthreads();
        sh[t] += x;
        __syncthreads();
    }
    if (i < NN) d_off[i] = sh[t] - v;
    if (t == 255) d_bsum[blockIdx.x] = sh[255];
}

__global__ void k_scan2() {
    __shared__ int sh[256];
    int t = threadIdx.x;
    int v = (t < NB) ? d_bsum[t] : 0;
    sh[t] = v;
    __syncthreads();
    for (int s = 1; s < 256; s <<= 1) {
        int x = (t >= s) ? sh[t - s] : 0;
        __syncthreads();
        sh[t] += x;
        __syncthreads();
    }
    if (t < NB) d_bsum[t] = sh[t] - v;
    if (t == 255) d_off[NN] = sh[255];
}

__global__ void k_scan3() {
    int i = blockIdx.x * 256 + threadIdx.x;
    if (i < NN) {
        int o = d_off[i] + d_bsum[blockIdx.x];
        d_off[i] = o;
        d_cur[i] = o;
    }
}

__global__ void k_fill(const int* __restrict__ ei) {
    int e = blockIdx.x * blockDim.x + threadIdx.x;
    if (e < NE) {
        int s = ei[e];
        int d = ei[NE + e];
        int p = atomicAdd(&d_cur[d], 1);
        d_csr[p] = s;
    }
}

// ---------------- SGEMM (FFMA2): C[N,64] = A[N,K] @ W[K,64] (+bias,relu,+pool) ----------------
template <int K, bool BIAS_RELU, bool POOL>
__global__ __launch_bounds__(256) void k_gemm(const float* __restrict__ A,
                                              const float* __restrict__ W,
                                              const float* __restrict__ bias,
                                              float* __restrict__ C,
                                              const int* __restrict__ batch,
                                              int lofs) {
    constexpr int KQ = K / 4;
    constexpr int SA = 130;                 // transposed-A row stride (even for b64 loads)
    extern __shared__ float sm[];
    float* Ws  = sm;                        // [K][64]
    float* AsT = sm + K * 64;               // [K][SA] transposed (k-major)
    int tid = threadIdx.x;
    int row0 = blockIdx.x * 128;

    for (int i = tid; i < K * 16; i += 256)
        ((float4*)Ws)[i] = ((const float4*)W)[i];
    for (int i = tid; i < 128 * KQ; i += 256) {
        int r  = i / KQ;
        int kq = (i % KQ) * 4;
        float4 v = make_float4(0.f, 0.f, 0.f, 0.f);
        int row = row0 + r;
        if (row < NN) v = *(const float4*)&A[(long)row * K + kq];
        AsT[(kq + 0) * SA + r] = v.x;
        AsT[(kq + 1) * SA + r] = v.y;
        AsT[(kq + 2) * SA + r] = v.z;
        AsT[(kq + 3) * SA + r] = v.w;
    }
    __syncthreads();

    int tx = tid & 15, ty = tid >> 4;
    int rb = ty * 8, cb = tx * 4;

    u64v acc[4][4];                          // 4 row-pairs x 4 cols
#pragma unroll
    for (int p = 0; p < 4; p++)
#pragma unroll
        for (int j = 0; j < 4; j++) acc[p][j] = pack2(0.f, 0.f);

#pragma unroll 4
    for (int k = 0; k < K; k++) {
        float4 w = *(float4*)&Ws[k * 64 + cb];
        u64v wx = pack2(w.x, w.x);
        u64v wy = pack2(w.y, w.y);
        u64v wz = pack2(w.z, w.z);
        u64v ww = pack2(w.w, w.w);
        const float* ar = &AsT[k * SA + rb];
#pragma unroll
        for (int p = 0; p < 4; p++) {
            u64v a = *(const u64v*)(ar + 2 * p);
            acc[p][0] = ffma2(a, wx, acc[p][0]);
            acc[p][1] = ffma2(a, wy, acc[p][1]);
            acc[p][2] = ffma2(a, wz, acc[p][2]);
            acc[p][3] = ffma2(a, ww, acc[p][3]);
        }
    }

    float4 bv;
    if (BIAS_RELU) bv = *(const float4*)&bias[cb];

    int   curb = -1;
    float4 rs = make_float4(0.f, 0.f, 0.f, 0.f);

#pragma unroll
    for (int p = 0; p < 4; p++) {
        float2 c0 = unpk2(acc[p][0]);
        float2 c1 = unpk2(acc[p][1]);
        float2 c2 = unpk2(acc[p][2]);
        float2 c3 = unpk2(acc[p][3]);
#pragma unroll
        for (int h = 0; h < 2; h++) {
            int row = row0 + rb + 2 * p + h;
            if (row >= NN) continue;
            float4 o;
            o.x = h ? c0.y : c0.x;
            o.y = h ? c1.y : c1.x;
            o.z = h ? c2.y : c2.x;
            o.w = h ? c3.y : c3.x;
            if (BIAS_RELU) {
                o.x = fmaxf(o.x + bv.x, 0.f);
                o.y = fmaxf(o.y + bv.y, 0.f);
                o.z = fmaxf(o.z + bv.z, 0.f);
                o.w = fmaxf(o.w + bv.w, 0.f);
            }
            *(float4*)&C[(long)row * 64 + cb] = o;
            if (POOL) {
                int b = batch[row];
                if (b != curb) {
                    if (curb >= 0) {
                        float* g = &d_G[curb * 192 + lofs + cb];
                        atomicAdd(g + 0, rs.x);
                        atomicAdd(g + 1, rs.y);
                        atomicAdd(g + 2, rs.z);
                        atomicAdd(g + 3, rs.w);
                    }
                    curb = b;
                    rs = make_float4(0.f, 0.f, 0.f, 0.f);
                }
                rs.x += o.x; rs.y += o.y; rs.z += o.z; rs.w += o.w;
            }
        }
    }
    if (POOL && curb >= 0) {
        float* g = &d_G[curb * 192 + lofs + cb];
        atomicAdd(g + 0, rs.x);
        atomicAdd(g + 1, rs.y);
        atomicAdd(g + 2, rs.z);
        atomicAdd(g + 3, rs.w);
    }
}

// ---------------- aggregation: M[n] = relu(P[n] + sum_{e->n} P[src(e)] + b1) ----------------
__global__ __launch_bounds__(256) void k_agg(const float* __restrict__ bias) {
    int warp = (blockIdx.x * blockDim.x + threadIdx.x) >> 5;
    int lane = threadIdx.x & 31;
    if (warp >= NN) return;
    int n = warp;
    int e0 = d_off[n], e1 = d_off[n + 1];
    const float2* P2 = (const float2*)d_P;
    float2 acc = make_float2(0.f, 0.f);
    int eb = e0;
    for (; eb + 32 <= e1; eb += 32) {
        int sl = d_csr[eb + lane];
#pragma unroll
        for (int j = 0; j < 32; ++j) {
            int s = __shfl_sync(0xffffffffu, sl, j);
            float2 v = __ldg(&P2[s * 32 + lane]);
            acc.x += v.x;
            acc.y += v.y;
        }
    }
    int rem = e1 - eb;
    if (rem > 0) {
        int sl = (lane < rem) ? d_csr[eb + lane] : 0;
        for (int j = 0; j < rem; ++j) {
            int s = __shfl_sync(0xffffffffu, sl, j);
            float2 v = __ldg(&P2[s * 32 + lane]);
            acc.x += v.x;
            acc.y += v.y;
        }
    }
    float2 p = P2[n * 32 + lane];
    float2 b = ((const float2*)bias)[lane];
    float2 o;
    o.x = fmaxf(p.x + acc.x + b.x, 0.f);
    o.y = fmaxf(p.y + acc.y + b.y, 0.f);
    ((float2*)d_M)[n * 32 + lane] = o;
}

// ---------------- tail ----------------
__global__ __launch_bounds__(64) void k_tail(const float* __restrict__ jk_w,
                                             const float* __restrict__ jk_b,
                                             const float* __restrict__ fw1,
                                             const float* __restrict__ fb1,
                                             const float* __restrict__ bng,
                                             const float* __restrict__ bnb,
                                             const float* __restrict__ bnm,
                                             const float* __restrict__ bnv,
                                             const float* __restrict__ fw2,
                                             const float* __restrict__ fb2,
                                             const float* __restrict__ ow,
                                             const float* __restrict__ ob,
                                             float* __restrict__ out) {
    int g = blockIdx.x, j = threadIdx.x;
    __shared__ float sv[192];
    __shared__ float t[64];
    sv[j]       = d_G[g * 192 + j];
    sv[j + 64]  = d_G[g * 192 + j + 64];
    sv[j + 128] = d_G[g * 192 + j + 128];
    __syncthreads();
    float cnt = (float)(d_gs[g + 1] - d_gs[g]);
    float a = cnt * jk_b[j];
    for (int k = 0; k < 192; k++) a += sv[k] * jk_w[k * 64 + j];
    __syncthreads();
    t[j] = a;
    __syncthreads();
    float a2 = fb1[j];
    for (int k = 0; k < 64; k++) a2 += t[k] * fw1[k * 64 + j];
    a2 = (a2 - bnm[j]) * rsqrtf(bnv[j] + 1e-5f) * bng[j] + bnb[j];
    a2 = fmaxf(a2, 0.f);
    __syncthreads();
    t[j] = a2;
    __syncthreads();
    float a3 = fb2[j];
    for (int k = 0; k < 64; k++) a3 += t[k] * fw2[k * 64 + j];
    __syncthreads();
    t[j] = a3;
    __syncthreads();
    if (j < ODIM) {
        float o = ob[j];
        for (int k = 0; k < 64; k++) o += t[k] * ow[k * ODIM + j];
        out[g * ODIM + j] = o;
    }
}

// ---------------- launcher ----------------
extern "C" void kernel_launch(void* const* d_in, const int* in_sizes, int n_in,
                              void* d_out, int out_size) {
    const float* x     = (const float*)d_in[0];
    const int*   ei    = (const int*)d_in[1];
    const int*   batch = (const int*)d_in[2];
    const float* w1[3] = {(const float*)d_in[3],  (const float*)d_in[7],  (const float*)d_in[11]};
    const float* b1[3] = {(const float*)d_in[4],  (const float*)d_in[8],  (const float*)d_in[12]};
    const float* w2[3] = {(const float*)d_in[5],  (const float*)d_in[9],  (const float*)d_in[13]};
    const float* b2[3] = {(const float*)d_in[6],  (const float*)d_in[10], (const float*)d_in[14]};
    const float* jk_w  = (const float*)d_in[15];
    const float* jk_b  = (const float*)d_in[16];
    const float* fw1   = (const float*)d_in[17];
    const float* fb1   = (const float*)d_in[18];
    const float* bng   = (const float*)d_in[19];
    const float* bnb   = (const float*)d_in[20];
    const float* bnm   = (const float*)d_in[21];
    const float* bnv   = (const float*)d_in[22];
    const float* fw2   = (const float*)d_in[23];
    const float* fb2   = (const float*)d_in[24];
    const float* ow    = (const float*)d_in[25];
    const float* ob    = (const float*)d_in[26];
    float* out = (float*)d_out;

    float *P, *M, *H[3];
    cudaGetSymbolAddress((void**)&P,    d_P);
    cudaGetSymbolAddress((void**)&M,    d_M);
    cudaGetSymbolAddress((void**)&H[0], d_H0);
    cudaGetSymbolAddress((void**)&H[1], d_H1);
    cudaGetSymbolAddress((void**)&H[2], d_H2);

    size_t s100 = (size_t)(100 * 64 + 100 * 130) * sizeof(float);
    size_t s64  = (size_t)(64 * 64 + 64 * 130) * sizeof(float);
    cudaFuncSetAttribute((const void*)k_gemm<100, false, false>,
                         cudaFuncAttributeMaxDynamicSharedMemorySize, (int)s100);
    cudaFuncSetAttribute((const void*)k_gemm<64, false, false>,
                         cudaFuncAttributeMaxDynamicSharedMemorySize, (int)s64);
    cudaFuncSetAttribute((const void*)k_gemm<64, true, true>,
                         cudaFuncAttributeMaxDynamicSharedMemorySize, (int)s64);

    // setup + CSR build
    k_setup<<<NB, 256>>>(batch);
    k_hist<<<(NE + 255) / 256, 256>>>(ei);
    k_scan1<<<NB, 256>>>();
    k_scan2<<<1, 256>>>();
    k_scan3<<<NB, 256>>>();
    k_fill<<<(NE + 255) / 256, 256>>>(ei);

    int gemm_blocks = (NN + 127) / 128;
    int agg_blocks  = (NN * 32 + 255) / 256;

    // layer 0 (K=100 input)
    k_gemm<100, false, false><<<gemm_blocks, 256, s100>>>(x, w1[0], nullptr, P, nullptr, 0);
    k_agg<<<agg_blocks, 256>>>(b1[0]);
    k_gemm<64, true, true><<<gemm_blocks, 256, s64>>>(M, w2[0], b2[0], H[0], batch, 0);

    // layers 1, 2 (pool fused into w2-gemm epilogue)
    for (int li = 1; li < 3; ++li) {
        k_gemm<64, false, false><<<gemm_blocks, 256, s64>>>(H[li - 1], w1[li], nullptr, P, nullptr, 0);
        k_agg<<<agg_blocks, 256>>>(b1[li]);
        k_gemm<64, true, true><<<gemm_blocks, 256, s64>>>(M, w2[li], b2[li], H[li], batch, li * 64);
    }

    // head
    k_tail<<<NG, 64>>>(jk_w, jk_b, fw1, fb1, bng, bnb, bnm, bnv, fw2, fb2, ow, ob, out);
}